// round 3
// baseline (speedup 1.0000x reference)
#include <cuda_runtime.h>
#include <cuda_bf16.h>
#include <stdint.h>

// Problem constants (dataset-fixed: N=100000, T=25, DEGS=4, G=512)
#define TPB   256
#define VEC   4                  // edges per thread per iteration
#define ITERS 4                  // iterations per thread
#define TILE  (TPB * VEC * ITERS)// edges per block = 4096
#define NMAX  100000
#define TT    625                // 25*25
#define GMAX  512

__device__ float4 g_nodes[NMAX];   // {pos.x, pos.y, pos.z, bitcast(atom_type)}
__device__ int    g_bnd[GMAX + 1]; // g_bnd[g] = first edge index of segment g
__device__ int    g_is64;          // 1 if index arrays are int64, 0 if int32

// ---------------------------------------------------------------------------
// Dtype detection: int32 data read as int64 yields values >= N.
// ---------------------------------------------------------------------------
__global__ void detect_kernel(const long long* __restrict__ mapping, int N)
{
    bool ok64 = true;
    #pragma unroll
    for (int i = 0; i < 8; i++) {
        long long v = mapping[i];
        if (v < 0 || v >= (long long)N) ok64 = false;
    }
    g_is64 = ok64 ? 1 : 0;
}

__device__ __forceinline__ int read_flag() { return *(volatile int*)&g_is64; }

// ---------------------------------------------------------------------------
// Prep: zero output, pack node table, binary-search segment boundaries
// ---------------------------------------------------------------------------
template <typename IdxT>
__global__ void prep_kernel(const float* __restrict__ pos,
                            const IdxT* __restrict__ atom_types,
                            const IdxT* __restrict__ batch,
                            float* __restrict__ out,
                            int N, int E, int G, int want64)
{
    if (read_flag() != want64) return;
    int i = blockIdx.x * blockDim.x + threadIdx.x;
    if (i < N) {
        float4 v;
        v.x = pos[3 * i + 0];
        v.y = pos[3 * i + 1];
        v.z = pos[3 * i + 2];
        v.w = __int_as_float((int)atom_types[i]);
        g_nodes[i] = v;
    }
    if (i < G) out[i] = 0.0f;
    if (i <= G) {
        int lo = 0, hi = E;
        IdxT target = (IdxT)i;
        while (lo < hi) {
            int mid = (int)(((unsigned)lo + (unsigned)hi) >> 1);
            if (batch[mid] < target) lo = mid + 1; else hi = mid;
        }
        g_bnd[i] = lo;
    }
}

// ---------------------------------------------------------------------------
// 4-index vector loads (16B transactions, streaming hint)
// ---------------------------------------------------------------------------
template <typename IdxT> struct Ld4;
template <> struct Ld4<int> {
    static __device__ __forceinline__ void load(const int* p, int o[4]) {
        int4 v = __ldcs((const int4*)p);
        o[0] = v.x; o[1] = v.y; o[2] = v.z; o[3] = v.w;
    }
};
template <> struct Ld4<long long> {
    static __device__ __forceinline__ void load(const long long* p, int o[4]) {
        longlong2 a = __ldcs((const longlong2*)p);
        longlong2 b = __ldcs((const longlong2*)(p + 2));
        o[0] = (int)a.x; o[1] = (int)a.y; o[2] = (int)b.x; o[3] = (int)b.y;
    }
};

// ---------------------------------------------------------------------------
// Main edge kernel: index loads pipelined 2 iterations ahead
// ---------------------------------------------------------------------------
template <typename IdxT>
__global__ void __launch_bounds__(TPB)
edge_kernel(const IdxT* __restrict__ map0,
            const IdxT* __restrict__ map1,
            const float* __restrict__ ks,     // [4,25,25]
            const float* __restrict__ v0t,    // [25,25]
            float* __restrict__ out,
            int E, int G, int want64)
{
    if (read_flag() != want64) return;

    __shared__ float4 sk[TT];       // k0..k3 per (t0,t1)
    __shared__ float  sv[TT];       // v0 per (t0,t1)
    __shared__ int    sbnd[GMAX + 1];

    const int tid = threadIdx.x;
    for (int i = tid; i < TT; i += TPB) {
        sk[i] = make_float4(ks[i], ks[TT + i], ks[2 * TT + i], ks[3 * TT + i]);
        sv[i] = v0t[i];
    }
    for (int i = tid; i <= G; i += TPB) sbnd[i] = g_bnd[i];
    __syncthreads();

    const int tile = blockIdx.x * TILE;
    if (tile >= E) return;

    // initial segment for this thread's first edge
    int firstE = tile + tid * VEC;
    if (firstE >= E) firstE = E - 1;
    int lo = 0, hi = G - 1;
    while (lo < hi) {
        int mid = (lo + hi) >> 1;
        if (sbnd[mid + 1] <= firstE) lo = mid + 1; else hi = mid;
    }
    int   seg    = lo;
    int   bndEnd = sbnd[seg + 1];
    float acc    = 0.0f;

    const float4* __restrict__ nodes = g_nodes;

#define HANDLE1(EIDX, VVAL)                                            \
    do {                                                               \
        if ((EIDX) >= bndEnd) {                                        \
            if (acc != 0.0f) atomicAdd(&out[seg], acc);                \
            acc = 0.0f;                                                \
            do { seg++; } while ((EIDX) >= sbnd[seg + 1]);             \
            bndEnd = sbnd[seg + 1];                                    \
        }                                                              \
        acc += (VVAL);                                                 \
    } while (0)

#define EDGE_V(II, JJ, VOUT)                                           \
    do {                                                               \
        float4 p = __ldg(nodes + (II));                                \
        float4 q = __ldg(nodes + (JJ));                                \
        float dx = p.x - q.x, dy = p.y - q.y, dz = p.z - q.z;          \
        float r2 = fmaf(dx, dx, fmaf(dy, dy, dz * dz));                \
        float x  = sqrtf(r2);                                          \
        int idx  = __float_as_int(p.w) * 25 + __float_as_int(q.w);     \
        float4 k = sk[idx];                                            \
        float  c = sv[idx];                                            \
        (VOUT) = fmaf(x, fmaf(x, fmaf(x, fmaf(x, k.w, k.z), k.y), k.x), c); \
    } while (0)

    if (tile + TILE <= E) {
        // ---- Full tile: fully unrolled, index loads prefetched depth-2 ----
        const int base = tile + tid * VEC;      // this thread's edge for it=0
        int ia[2][VEC], ja[2][VEC];
        Ld4<IdxT>::load(map0 + base, ia[0]);
        Ld4<IdxT>::load(map1 + base, ja[0]);
        Ld4<IdxT>::load(map0 + base + TPB * VEC, ia[1]);
        Ld4<IdxT>::load(map1 + base + TPB * VEC, ja[1]);

        #pragma unroll
        for (int it = 0; it < ITERS; ++it) {
            const int cur = it & 1;
            const int e   = base + it * (TPB * VEC);

            // issue gathers for this iteration (indices already resident)
            float4 p0 = __ldg(nodes + ia[cur][0]);
            float4 q0 = __ldg(nodes + ja[cur][0]);
            float4 p1 = __ldg(nodes + ia[cur][1]);
            float4 q1 = __ldg(nodes + ja[cur][1]);
            float4 p2 = __ldg(nodes + ia[cur][2]);
            float4 q2 = __ldg(nodes + ja[cur][2]);
            float4 p3 = __ldg(nodes + ia[cur][3]);
            float4 q3 = __ldg(nodes + ja[cur][3]);

            // prefetch indices for iteration it+2 into the slot just consumed
            if (it + 2 < ITERS) {
                Ld4<IdxT>::load(map0 + base + (it + 2) * (TPB * VEC), ia[cur]);
                Ld4<IdxT>::load(map1 + base + (it + 2) * (TPB * VEC), ja[cur]);
            }

            float dx, dy, dz, r2, x;
            int idx; float4 k; float c;
            float V0, V1, V2, V3;

            dx = p0.x - q0.x; dy = p0.y - q0.y; dz = p0.z - q0.z;
            r2 = fmaf(dx, dx, fmaf(dy, dy, dz * dz)); x = sqrtf(r2);
            idx = __float_as_int(p0.w) * 25 + __float_as_int(q0.w);
            k = sk[idx]; c = sv[idx];
            V0 = fmaf(x, fmaf(x, fmaf(x, fmaf(x, k.w, k.z), k.y), k.x), c);

            dx = p1.x - q1.x; dy = p1.y - q1.y; dz = p1.z - q1.z;
            r2 = fmaf(dx, dx, fmaf(dy, dy, dz * dz)); x = sqrtf(r2);
            idx = __float_as_int(p1.w) * 25 + __float_as_int(q1.w);
            k = sk[idx]; c = sv[idx];
            V1 = fmaf(x, fmaf(x, fmaf(x, fmaf(x, k.w, k.z), k.y), k.x), c);

            dx = p2.x - q2.x; dy = p2.y - q2.y; dz = p2.z - q2.z;
            r2 = fmaf(dx, dx, fmaf(dy, dy, dz * dz)); x = sqrtf(r2);
            idx = __float_as_int(p2.w) * 25 + __float_as_int(q2.w);
            k = sk[idx]; c = sv[idx];
            V2 = fmaf(x, fmaf(x, fmaf(x, fmaf(x, k.w, k.z), k.y), k.x), c);

            dx = p3.x - q3.x; dy = p3.y - q3.y; dz = p3.z - q3.z;
            r2 = fmaf(dx, dx, fmaf(dy, dy, dz * dz)); x = sqrtf(r2);
            idx = __float_as_int(p3.w) * 25 + __float_as_int(q3.w);
            k = sk[idx]; c = sv[idx];
            V3 = fmaf(x, fmaf(x, fmaf(x, fmaf(x, k.w, k.z), k.y), k.x), c);

            // segment accumulation: fast path when whole group is inside segment
            if (e + 3 < bndEnd) {
                acc += (V0 + V1) + (V2 + V3);
            } else {
                HANDLE1(e + 0, V0);
                HANDLE1(e + 1, V1);
                HANDLE1(e + 2, V2);
                HANDLE1(e + 3, V3);
            }
        }
    } else {
        // ---- Partial tile: simple scalar path ----
        for (int it = 0; it < ITERS; ++it) {
            int e = tile + it * (TPB * VEC) + tid * VEC;
            for (int kk = 0; kk < VEC; ++kk) {
                int ee = e + kk;
                if (ee >= E) break;
                int ii = (int)__ldcs(map0 + ee);
                int jj = (int)__ldcs(map1 + ee);
                float V;
                EDGE_V(ii, jj, V);
                HANDLE1(ee, V);
            }
        }
    }

    if (acc != 0.0f) atomicAdd(&out[seg], acc);
#undef HANDLE1
#undef EDGE_V
}

// ---------------------------------------------------------------------------
// Launch
// ---------------------------------------------------------------------------
extern "C" void kernel_launch(void* const* d_in, const int* in_sizes, int n_in,
                              void* d_out, int out_size)
{
    // Inputs: pos, ks, v_0, mapping, atom_types, mapping_batch[, n_graphs]
    const float* pos = (const float*)d_in[0];
    const float* ks  = (const float*)d_in[1];
    const float* v0t = (const float*)d_in[2];
    const void*  mapping    = d_in[3];
    const void*  atom_types = d_in[4];
    const void*  batch      = d_in[5];

    const int N = in_sizes[0] / 3;
    const int E = in_sizes[3] / 2;
    const int G = out_size;           // 512 segments

    float* out = (float*)d_out;

    // 1. Detect index dtype (int32 vs int64)
    detect_kernel<<<1, 1>>>((const long long*)mapping, N);

    // 2. Prep (both variants; mismatched one exits immediately)
    int prepThreads = (N > G + 1) ? N : (G + 1);
    int prepBlocks  = (prepThreads + TPB - 1) / TPB;
    prep_kernel<int><<<prepBlocks, TPB>>>(
        pos, (const int*)atom_types, (const int*)batch, out, N, E, G, 0);
    prep_kernel<long long><<<prepBlocks, TPB>>>(
        pos, (const long long*)atom_types, (const long long*)batch, out, N, E, G, 1);

    // 3. Main edge kernel (both variants)
    int blocks = (E + TILE - 1) / TILE;
    edge_kernel<int><<<blocks, TPB>>>(
        (const int*)mapping, (const int*)mapping + E,
        ks, v0t, out, E, G, 0);
    edge_kernel<long long><<<blocks, TPB>>>(
        (const long long*)mapping, (const long long*)mapping + E,
        ks, v0t, out, E, G, 1);
}

// round 5
// speedup vs baseline: 1.4156x; 1.4156x over previous
#include <cuda_runtime.h>
#include <cuda_bf16.h>
#include <stdint.h>

// Dataset-fixed: N=100000, T=25, DEGS=4, G=512, E=8000000
#define TPB    256
#define VEC    4                    // edges per thread per inner iteration
#define CHUNK  2048                 // edges per pipeline stage
#define STAGES 2
#define CITERS (CHUNK / (TPB * VEC))     // 2 inner iterations per chunk
#define NCHUNK 4                    // chunks per block
#define SPAN   (CHUNK * NCHUNK)     // 8192 edges per block
#define NMAX   100000
#define TT     625                  // 25*25
#define GMAX   512

__device__ float4 g_nodes[NMAX];    // {pos.x, pos.y, pos.z, bitcast(atom_type)}
__device__ int    g_bnd[GMAX + 1];  // g_bnd[g] = first edge index of segment g
__device__ int    g_is64;           // 1 if index arrays are int64, 0 if int32

// ---------------------------------------------------------------------------
// cp.async helpers
// ---------------------------------------------------------------------------
__device__ __forceinline__ uint32_t smem_u32(const void* p) {
    return (uint32_t)__cvta_generic_to_shared(p);
}
__device__ __forceinline__ void cp_async16(uint32_t dst, const void* src) {
    asm volatile("cp.async.cg.shared.global [%0], [%1], 16;" :: "r"(dst), "l"(src));
}
__device__ __forceinline__ void cp_commit() {
    asm volatile("cp.async.commit_group;");
}
template <int N>
__device__ __forceinline__ void cp_wait() {
    asm volatile("cp.async.wait_group %0;" :: "n"(N));
}

// ---------------------------------------------------------------------------
// Dtype detection: int32 data read as int64 yields values >= N.
// ---------------------------------------------------------------------------
__global__ void detect_kernel(const long long* __restrict__ mapping, int N)
{
    bool ok64 = true;
    #pragma unroll
    for (int i = 0; i < 8; i++) {
        long long v = mapping[i];
        if (v < 0 || v >= (long long)N) ok64 = false;
    }
    g_is64 = ok64 ? 1 : 0;
}
__device__ __forceinline__ int read_flag() { return *(volatile int*)&g_is64; }

// ---------------------------------------------------------------------------
// Prep: zero output, pack node table, binary-search segment boundaries
// ---------------------------------------------------------------------------
template <typename IdxT>
__global__ void prep_kernel(const float* __restrict__ pos,
                            const IdxT* __restrict__ atom_types,
                            const IdxT* __restrict__ batch,
                            float* __restrict__ out,
                            int N, int E, int G, int want64)
{
    if (read_flag() != want64) return;
    int i = blockIdx.x * blockDim.x + threadIdx.x;
    if (i < N) {
        float4 v;
        v.x = pos[3 * i + 0];
        v.y = pos[3 * i + 1];
        v.z = pos[3 * i + 2];
        v.w = __int_as_float((int)atom_types[i]);
        g_nodes[i] = v;
    }
    if (i < G) out[i] = 0.0f;
    if (i <= G) {
        int lo = 0, hi = E;
        IdxT target = (IdxT)i;
        while (lo < hi) {
            int mid = (int)(((unsigned)lo + (unsigned)hi) >> 1);
            if (batch[mid] < target) lo = mid + 1; else hi = mid;
        }
        g_bnd[i] = lo;
    }
}

// ---------------------------------------------------------------------------
// Shared EDGE_V / HANDLE fragments
// ---------------------------------------------------------------------------
#define EDGE_V(II, JJ, VOUT)                                               \
    do {                                                                   \
        float4 p = __ldg(nodes + (II));                                    \
        float4 q = __ldg(nodes + (JJ));                                    \
        float dx = p.x - q.x, dy = p.y - q.y, dz = p.z - q.z;              \
        float r2 = fmaf(dx, dx, fmaf(dy, dy, dz * dz));                    \
        float x  = sqrtf(r2);                                              \
        int idx  = __float_as_int(p.w) * 25 + __float_as_int(q.w);         \
        float4 k = sk[idx];                                                \
        float  c = sv[idx];                                                \
        (VOUT) = fmaf(x, fmaf(x, fmaf(x, fmaf(x, k.w, k.z), k.y), k.x), c);\
    } while (0)

#define HANDLE1(EIDX, VVAL)                                                \
    do {                                                                   \
        if ((EIDX) >= bndEnd) {                                            \
            if (acc != 0.0f) atomicAdd(&out[seg], acc);                    \
            acc = 0.0f;                                                    \
            do { seg++; } while ((EIDX) >= sbnd[seg + 1]);                 \
            bndEnd = sbnd[seg + 1];                                        \
        }                                                                  \
        acc += (VVAL);                                                     \
    } while (0)

// ---------------------------------------------------------------------------
// Main int32 edge kernel: cp.async-staged index stream, double buffered
// ---------------------------------------------------------------------------
__global__ void __launch_bounds__(TPB, 4)
edge_kernel32(const int* __restrict__ map0,
              const int* __restrict__ map1,
              const float* __restrict__ ks,     // [4,25,25]
              const float* __restrict__ v0t,    // [25,25]
              float* __restrict__ out,
              int E, int G)
{
    if (read_flag() != 0) return;

    __shared__ float4 sk[TT];
    __shared__ float  sv[TT];
    __shared__ int    sbnd[GMAX + 1];
    __shared__ __align__(16) int s_i0[STAGES][CHUNK];   // 16B-aligned for cp.async/int4
    __shared__ __align__(16) int s_i1[STAGES][CHUNK];

    const int tid = threadIdx.x;
    for (int i = tid; i < TT; i += TPB) {
        sk[i] = make_float4(ks[i], ks[TT + i], ks[2 * TT + i], ks[3 * TT + i]);
        sv[i] = v0t[i];
    }
    for (int i = tid; i <= G; i += TPB) sbnd[i] = g_bnd[i];
    __syncthreads();

    const int span = blockIdx.x * SPAN;
    if (span >= E) return;

    // initial segment for this thread's first edge
    int firstE = span + tid * VEC;
    if (firstE >= E) firstE = E - 1;
    int lo = 0, hi = G - 1;
    while (lo < hi) {
        int mid = (lo + hi) >> 1;
        if (sbnd[mid + 1] <= firstE) lo = mid + 1; else hi = mid;
    }
    int   seg    = lo;
    int   bndEnd = sbnd[seg + 1];
    float acc    = 0.0f;

    const float4* __restrict__ nodes = g_nodes;

    if (span + SPAN <= E) {
        // ================= Pipelined full-span path =================
        auto issue_stage = [&](int chunk_base, int buf) {
            #pragma unroll
            for (int k = 0; k < CHUNK / (TPB * 4); ++k) {   // = 2
                int piece = tid + k * TPB;                  // 16B piece index
                cp_async16(smem_u32(&s_i0[buf][piece * 4]), map0 + chunk_base + piece * 4);
                cp_async16(smem_u32(&s_i1[buf][piece * 4]), map1 + chunk_base + piece * 4);
            }
        };

        // prologue: fill both stages
        issue_stage(span, 0);               cp_commit();
        issue_stage(span + CHUNK, 1);       cp_commit();

        for (int c = 0; c < NCHUNK; ++c) {
            cp_wait<STAGES - 1>();          // oldest group (chunk c) done
            __syncthreads();
            const int buf = c & (STAGES - 1);
            const int cbase = span + c * CHUNK;

            #pragma unroll
            for (int it = 0; it < CITERS; ++it) {
                const int off = it * (TPB * VEC) + tid * VEC;
                const int e   = cbase + off;

                int4 ia = *(const int4*)&s_i0[buf][off];
                int4 ja = *(const int4*)&s_i1[buf][off];

                float V0, V1, V2, V3;
                EDGE_V(ia.x, ja.x, V0);
                EDGE_V(ia.y, ja.y, V1);
                EDGE_V(ia.z, ja.z, V2);
                EDGE_V(ia.w, ja.w, V3);

                if (e + 3 < bndEnd) {
                    acc += (V0 + V1) + (V2 + V3);
                } else {
                    HANDLE1(e + 0, V0);
                    HANDLE1(e + 1, V1);
                    HANDLE1(e + 2, V2);
                    HANDLE1(e + 3, V3);
                }
            }
            __syncthreads();                // done reading buf before refill
            int next = c + STAGES;
            if (next < NCHUNK) issue_stage(span + next * CHUNK, buf);
            cp_commit();                    // keep group accounting uniform
        }
    } else {
        // ================= Partial-span scalar path =================
        for (int it = 0; it < SPAN / (TPB * VEC); ++it) {
            int e = span + it * (TPB * VEC) + tid * VEC;
            for (int kk = 0; kk < VEC; ++kk) {
                int ee = e + kk;
                if (ee >= E) break;
                int ii = __ldcs(map0 + ee);
                int jj = __ldcs(map1 + ee);
                float V;
                EDGE_V(ii, jj, V);
                HANDLE1(ee, V);
            }
        }
    }

    if (acc != 0.0f) atomicAdd(&out[seg], acc);
}

// ---------------------------------------------------------------------------
// int64 fallback (simple R2-style; early-exits when data is int32)
// ---------------------------------------------------------------------------
__global__ void __launch_bounds__(TPB)
edge_kernel64(const long long* __restrict__ map0,
              const long long* __restrict__ map1,
              const float* __restrict__ ks,
              const float* __restrict__ v0t,
              float* __restrict__ out,
              int E, int G)
{
    if (read_flag() != 1) return;

    __shared__ float4 sk[TT];
    __shared__ float  sv[TT];
    __shared__ int    sbnd[GMAX + 1];

    const int tid = threadIdx.x;
    for (int i = tid; i < TT; i += TPB) {
        sk[i] = make_float4(ks[i], ks[TT + i], ks[2 * TT + i], ks[3 * TT + i]);
        sv[i] = v0t[i];
    }
    for (int i = tid; i <= G; i += TPB) sbnd[i] = g_bnd[i];
    __syncthreads();

    const int span = blockIdx.x * SPAN;
    if (span >= E) return;

    int firstE = span + tid * VEC;
    if (firstE >= E) firstE = E - 1;
    int lo = 0, hi = G - 1;
    while (lo < hi) {
        int mid = (lo + hi) >> 1;
        if (sbnd[mid + 1] <= firstE) lo = mid + 1; else hi = mid;
    }
    int   seg    = lo;
    int   bndEnd = sbnd[seg + 1];
    float acc    = 0.0f;

    const float4* __restrict__ nodes = g_nodes;

    for (int it = 0; it < SPAN / (TPB * VEC); ++it) {
        int e = span + it * (TPB * VEC) + tid * VEC;
        if (e >= E) break;
        if (e + VEC <= E) {
            longlong2 a0 = __ldcs((const longlong2*)(map0 + e));
            longlong2 a1 = __ldcs((const longlong2*)(map0 + e + 2));
            longlong2 b0 = __ldcs((const longlong2*)(map1 + e));
            longlong2 b1 = __ldcs((const longlong2*)(map1 + e + 2));
            float V0, V1, V2, V3;
            EDGE_V((int)a0.x, (int)b0.x, V0);
            EDGE_V((int)a0.y, (int)b0.y, V1);
            EDGE_V((int)a1.x, (int)b1.x, V2);
            EDGE_V((int)a1.y, (int)b1.y, V3);
            if (e + 3 < bndEnd) {
                acc += (V0 + V1) + (V2 + V3);
            } else {
                HANDLE1(e + 0, V0);
                HANDLE1(e + 1, V1);
                HANDLE1(e + 2, V2);
                HANDLE1(e + 3, V3);
            }
        } else {
            for (int kk = 0; kk < VEC; ++kk) {
                int ee = e + kk;
                if (ee >= E) break;
                int ii = (int)__ldcs(map0 + ee);
                int jj = (int)__ldcs(map1 + ee);
                float V;
                EDGE_V(ii, jj, V);
                HANDLE1(ee, V);
            }
        }
    }
    if (acc != 0.0f) atomicAdd(&out[seg], acc);
}

// ---------------------------------------------------------------------------
// Launch
// ---------------------------------------------------------------------------
extern "C" void kernel_launch(void* const* d_in, const int* in_sizes, int n_in,
                              void* d_out, int out_size)
{
    const float* pos = (const float*)d_in[0];
    const float* ks  = (const float*)d_in[1];
    const float* v0t = (const float*)d_in[2];
    const void*  mapping    = d_in[3];
    const void*  atom_types = d_in[4];
    const void*  batch      = d_in[5];

    const int N = in_sizes[0] / 3;
    const int E = in_sizes[3] / 2;
    const int G = out_size;

    float* out = (float*)d_out;

    detect_kernel<<<1, 1>>>((const long long*)mapping, N);

    int prepThreads = (N > G + 1) ? N : (G + 1);
    int prepBlocks  = (prepThreads + TPB - 1) / TPB;
    prep_kernel<int><<<prepBlocks, TPB>>>(
        pos, (const int*)atom_types, (const int*)batch, out, N, E, G, 0);
    prep_kernel<long long><<<prepBlocks, TPB>>>(
        pos, (const long long*)atom_types, (const long long*)batch, out, N, E, G, 1);

    int blocks = (E + SPAN - 1) / SPAN;
    edge_kernel32<<<blocks, TPB>>>(
        (const int*)mapping, (const int*)mapping + E, ks, v0t, out, E, G);
    edge_kernel64<<<blocks, TPB>>>(
        (const long long*)mapping, (const long long*)mapping + E, ks, v0t, out, E, G);
}

// round 6
// speedup vs baseline: 2.4381x; 1.7223x over previous
#include <cuda_runtime.h>
#include <cuda_bf16.h>
#include <stdint.h>

// Dataset-fixed: N=100000, T=25, DEGS=4, G=512, E=8000000
#define TPB    256
#define VEC    4                     // edges per thread per inner iteration
#define ITERS  2                     // inner iterations per tile
#define TILE   (TPB * VEC * ITERS)   // 2048 edges per block
#define NMAX   100000
#define TT     625                   // 25*25
#define GMAX   512

__device__ float4 g_nodes[NMAX];    // {pos.x, pos.y, pos.z, bitcast(atom_type)}
__device__ int    g_bnd[GMAX + 1];  // g_bnd[g] = first edge index of segment g
__device__ int    g_is64;           // 1 if index arrays are int64, 0 if int32

// ---------------------------------------------------------------------------
// Dtype detection: int32 data read as int64 yields values >= N.
// ---------------------------------------------------------------------------
__global__ void detect_kernel(const long long* __restrict__ mapping, int N)
{
    bool ok64 = true;
    #pragma unroll
    for (int i = 0; i < 8; i++) {
        long long v = mapping[i];
        if (v < 0 || v >= (long long)N) ok64 = false;
    }
    g_is64 = ok64 ? 1 : 0;
}
__device__ __forceinline__ int read_flag() { return *(volatile int*)&g_is64; }

// ---------------------------------------------------------------------------
// Prep: zero output, pack node table, binary-search segment boundaries
// ---------------------------------------------------------------------------
template <typename IdxT>
__global__ void prep_kernel(const float* __restrict__ pos,
                            const IdxT* __restrict__ atom_types,
                            const IdxT* __restrict__ batch,
                            float* __restrict__ out,
                            int N, int E, int G, int want64)
{
    if (read_flag() != want64) return;
    int i = blockIdx.x * blockDim.x + threadIdx.x;
    if (i < N) {
        float4 v;
        v.x = pos[3 * i + 0];
        v.y = pos[3 * i + 1];
        v.z = pos[3 * i + 2];
        v.w = __int_as_float((int)atom_types[i]);
        g_nodes[i] = v;
    }
    if (i < G) out[i] = 0.0f;
    if (i <= G) {
        int lo = 0, hi = E;
        IdxT target = (IdxT)i;
        while (lo < hi) {
            int mid = (int)(((unsigned)lo + (unsigned)hi) >> 1);
            if (batch[mid] < target) lo = mid + 1; else hi = mid;
        }
        g_bnd[i] = lo;
    }
}

// ---------------------------------------------------------------------------
// Shared fragments
// ---------------------------------------------------------------------------
#define EDGE_V(II, JJ, VOUT)                                               \
    do {                                                                   \
        float4 p = __ldg(nodes + (II));                                    \
        float4 q = __ldg(nodes + (JJ));                                    \
        float dx = p.x - q.x, dy = p.y - q.y, dz = p.z - q.z;              \
        float r2 = fmaf(dx, dx, fmaf(dy, dy, dz * dz));                    \
        float x  = sqrtf(r2);                                              \
        int idx  = __float_as_int(p.w) * 25 + __float_as_int(q.w);         \
        float4 k = sk[idx];                                                \
        float  c = sv[idx];                                                \
        (VOUT) = fmaf(x, fmaf(x, fmaf(x, fmaf(x, k.w, k.z), k.y), k.x), c);\
    } while (0)

#define HANDLE1(EIDX, VVAL)                                                \
    do {                                                                   \
        if ((EIDX) >= bndEnd) {                                            \
            if (acc != 0.0f) atomicAdd(&out[seg], acc);                    \
            acc = 0.0f;                                                    \
            do { seg++; } while ((EIDX) >= sbnd[seg + 1]);                 \
            bndEnd = sbnd[seg + 1];                                        \
        }                                                                  \
        acc += (VVAL);                                                     \
    } while (0)

// Warp-aggregated final flush: one atomic per warp when segment is uniform.
__device__ __forceinline__ void flush_acc(float* __restrict__ out, int seg, float acc)
{
    const unsigned full = 0xFFFFFFFFu;
    int seg0 = __shfl_sync(full, seg, 0);
    bool uniform = __all_sync(full, seg == seg0);
    if (uniform) {
        #pragma unroll
        for (int o = 16; o > 0; o >>= 1)
            acc += __shfl_xor_sync(full, acc, o);
        if ((threadIdx.x & 31) == 0 && acc != 0.0f)
            atomicAdd(&out[seg0], acc);
    } else {
        if (acc != 0.0f) atomicAdd(&out[seg], acc);
    }
}

// ---------------------------------------------------------------------------
// Main int32 edge kernel
// ---------------------------------------------------------------------------
__global__ void __launch_bounds__(TPB, 6)
edge_kernel32(const int* __restrict__ map0,
              const int* __restrict__ map1,
              const float* __restrict__ ks,     // [4,25,25]
              const float* __restrict__ v0t,    // [25,25]
              float* __restrict__ out,
              int E, int G)
{
    if (read_flag() != 0) return;

    __shared__ float4 sk[TT];
    __shared__ float  sv[TT];
    __shared__ int    sbnd[GMAX + 1];

    const int tid = threadIdx.x;
    for (int i = tid; i < TT; i += TPB) {
        sk[i] = make_float4(ks[i], ks[TT + i], ks[2 * TT + i], ks[3 * TT + i]);
        sv[i] = v0t[i];
    }
    for (int i = tid; i <= G; i += TPB) sbnd[i] = g_bnd[i];
    __syncthreads();

    const int tile = blockIdx.x * TILE;
    if (tile >= E) return;

    // initial segment for this thread's first edge
    int firstE = tile + tid * VEC;
    if (firstE >= E) firstE = E - 1;
    int lo = 0, hi = G - 1;
    while (lo < hi) {
        int mid = (lo + hi) >> 1;
        if (sbnd[mid + 1] <= firstE) lo = mid + 1; else hi = mid;
    }
    int   seg    = lo;
    int   bndEnd = sbnd[seg + 1];
    float acc    = 0.0f;

    const float4* __restrict__ nodes = g_nodes;

    if (tile + TILE <= E) {
        #pragma unroll
        for (int it = 0; it < ITERS; ++it) {
            const int e = tile + it * (TPB * VEC) + tid * VEC;
            int4 ia = __ldcs((const int4*)(map0 + e));
            int4 ja = __ldcs((const int4*)(map1 + e));

            float V0, V1, V2, V3;
            EDGE_V(ia.x, ja.x, V0);
            EDGE_V(ia.y, ja.y, V1);
            EDGE_V(ia.z, ja.z, V2);
            EDGE_V(ia.w, ja.w, V3);

            if (e + 3 < bndEnd) {
                acc += (V0 + V1) + (V2 + V3);
            } else {
                HANDLE1(e + 0, V0);
                HANDLE1(e + 1, V1);
                HANDLE1(e + 2, V2);
                HANDLE1(e + 3, V3);
            }
        }
    } else {
        for (int it = 0; it < ITERS; ++it) {
            int e = tile + it * (TPB * VEC) + tid * VEC;
            for (int kk = 0; kk < VEC; ++kk) {
                int ee = e + kk;
                if (ee >= E) break;
                int ii = __ldcs(map0 + ee);
                int jj = __ldcs(map1 + ee);
                float V;
                EDGE_V(ii, jj, V);
                HANDLE1(ee, V);
            }
        }
    }

    flush_acc(out, seg, acc);
}

// ---------------------------------------------------------------------------
// int64 fallback (early-exits when data is int32)
// ---------------------------------------------------------------------------
__global__ void __launch_bounds__(TPB)
edge_kernel64(const long long* __restrict__ map0,
              const long long* __restrict__ map1,
              const float* __restrict__ ks,
              const float* __restrict__ v0t,
              float* __restrict__ out,
              int E, int G)
{
    if (read_flag() != 1) return;

    __shared__ float4 sk[TT];
    __shared__ float  sv[TT];
    __shared__ int    sbnd[GMAX + 1];

    const int tid = threadIdx.x;
    for (int i = tid; i < TT; i += TPB) {
        sk[i] = make_float4(ks[i], ks[TT + i], ks[2 * TT + i], ks[3 * TT + i]);
        sv[i] = v0t[i];
    }
    for (int i = tid; i <= G; i += TPB) sbnd[i] = g_bnd[i];
    __syncthreads();

    const int tile = blockIdx.x * TILE;
    if (tile >= E) return;

    int firstE = tile + tid * VEC;
    if (firstE >= E) firstE = E - 1;
    int lo = 0, hi = G - 1;
    while (lo < hi) {
        int mid = (lo + hi) >> 1;
        if (sbnd[mid + 1] <= firstE) lo = mid + 1; else hi = mid;
    }
    int   seg    = lo;
    int   bndEnd = sbnd[seg + 1];
    float acc    = 0.0f;

    const float4* __restrict__ nodes = g_nodes;

    for (int it = 0; it < ITERS; ++it) {
        int e = tile + it * (TPB * VEC) + tid * VEC;
        if (e >= E) break;
        if (e + VEC <= E) {
            longlong2 a0 = __ldcs((const longlong2*)(map0 + e));
            longlong2 a1 = __ldcs((const longlong2*)(map0 + e + 2));
            longlong2 b0 = __ldcs((const longlong2*)(map1 + e));
            longlong2 b1 = __ldcs((const longlong2*)(map1 + e + 2));
            float V0, V1, V2, V3;
            EDGE_V((int)a0.x, (int)b0.x, V0);
            EDGE_V((int)a0.y, (int)b0.y, V1);
            EDGE_V((int)a1.x, (int)b1.x, V2);
            EDGE_V((int)a1.y, (int)b1.y, V3);
            if (e + 3 < bndEnd) {
                acc += (V0 + V1) + (V2 + V3);
            } else {
                HANDLE1(e + 0, V0);
                HANDLE1(e + 1, V1);
                HANDLE1(e + 2, V2);
                HANDLE1(e + 3, V3);
            }
        } else {
            for (int kk = 0; kk < VEC; ++kk) {
                int ee = e + kk;
                if (ee >= E) break;
                int ii = (int)__ldcs(map0 + ee);
                int jj = (int)__ldcs(map1 + ee);
                float V;
                EDGE_V(ii, jj, V);
                HANDLE1(ee, V);
            }
        }
    }
    if (acc != 0.0f) atomicAdd(&out[seg], acc);
}

// ---------------------------------------------------------------------------
// Launch
// ---------------------------------------------------------------------------
extern "C" void kernel_launch(void* const* d_in, const int* in_sizes, int n_in,
                              void* d_out, int out_size)
{
    const float* pos = (const float*)d_in[0];
    const float* ks  = (const float*)d_in[1];
    const float* v0t = (const float*)d_in[2];
    const void*  mapping    = d_in[3];
    const void*  atom_types = d_in[4];
    const void*  batch      = d_in[5];

    const int N = in_sizes[0] / 3;
    const int E = in_sizes[3] / 2;
    const int G = out_size;

    float* out = (float*)d_out;

    detect_kernel<<<1, 1>>>((const long long*)mapping, N);

    int prepThreads = (N > G + 1) ? N : (G + 1);
    int prepBlocks  = (prepThreads + TPB - 1) / TPB;
    prep_kernel<int><<<prepBlocks, TPB>>>(
        pos, (const int*)atom_types, (const int*)batch, out, N, E, G, 0);
    prep_kernel<long long><<<prepBlocks, TPB>>>(
        pos, (const long long*)atom_types, (const long long*)batch, out, N, E, G, 1);

    int blocks = (E + TILE - 1) / TILE;
    edge_kernel32<<<blocks, TPB>>>(
        (const int*)mapping, (const int*)mapping + E, ks, v0t, out, E, G);
    edge_kernel64<<<blocks, TPB>>>(
        (const long long*)mapping, (const long long*)mapping + E, ks, v0t, out, E, G);
}

// round 7
// speedup vs baseline: 2.5936x; 1.0638x over previous
#include <cuda_runtime.h>
#include <cuda_bf16.h>
#include <stdint.h>

// Dataset-fixed: N=100000, T=25, DEGS=4, G=512, E=8000000
#define TPB    256
#define VEC    4                     // edges per thread per inner iteration
#define ITERS  4                     // inner iterations per tile
#define TILE   (TPB * VEC * ITERS)   // 4096 edges per block
#define NMAX   100000
#define TT     625                   // 25*25
#define GMAX   512

__device__ float4 g_nodes[NMAX];    // {pos.x, pos.y, pos.z, bitcast(atom_type)}
__device__ int    g_bnd[GMAX + 1];  // g_bnd[g] = first edge index of segment g
__device__ int    g_is64;           // 1 if index arrays are int64, 0 if int32

// ---------------------------------------------------------------------------
// Dtype detection: int32 data read as int64 yields values >= N.
// ---------------------------------------------------------------------------
__global__ void detect_kernel(const long long* __restrict__ mapping, int N)
{
    bool ok64 = true;
    #pragma unroll
    for (int i = 0; i < 8; i++) {
        long long v = mapping[i];
        if (v < 0 || v >= (long long)N) ok64 = false;
    }
    g_is64 = ok64 ? 1 : 0;
}
__device__ __forceinline__ int read_flag() { return *(volatile int*)&g_is64; }

// ---------------------------------------------------------------------------
// Prep: zero output, pack node table, binary-search segment boundaries
// ---------------------------------------------------------------------------
template <typename IdxT>
__global__ void prep_kernel(const float* __restrict__ pos,
                            const IdxT* __restrict__ atom_types,
                            const IdxT* __restrict__ batch,
                            float* __restrict__ out,
                            int N, int E, int G, int want64)
{
    if (read_flag() != want64) return;
    int i = blockIdx.x * blockDim.x + threadIdx.x;
    if (i < N) {
        float4 v;
        v.x = pos[3 * i + 0];
        v.y = pos[3 * i + 1];
        v.z = pos[3 * i + 2];
        v.w = __int_as_float((int)atom_types[i]);
        g_nodes[i] = v;
    }
    if (i < G) out[i] = 0.0f;
    if (i <= G) {
        int lo = 0, hi = E;
        IdxT target = (IdxT)i;
        while (lo < hi) {
            int mid = (int)(((unsigned)lo + (unsigned)hi) >> 1);
            if (batch[mid] < target) lo = mid + 1; else hi = mid;
        }
        g_bnd[i] = lo;
    }
}

// ---------------------------------------------------------------------------
// Shared fragments
// ---------------------------------------------------------------------------
#define EDGE_V(II, JJ, VOUT)                                               \
    do {                                                                   \
        float4 p = __ldg(nodes + (II));                                    \
        float4 q = __ldg(nodes + (JJ));                                    \
        float dx = p.x - q.x, dy = p.y - q.y, dz = p.z - q.z;              \
        float r2 = fmaf(dx, dx, fmaf(dy, dy, dz * dz));                    \
        float x  = sqrtf(r2);                                              \
        int idx  = __float_as_int(p.w) * 25 + __float_as_int(q.w);         \
        float4 k = sk[idx];                                                \
        float  c = sv[idx];                                                \
        (VOUT) = fmaf(x, fmaf(x, fmaf(x, fmaf(x, k.w, k.z), k.y), k.x), c);\
    } while (0)

#define HANDLE1(EIDX, VVAL)                                                \
    do {                                                                   \
        if ((EIDX) >= bndEnd) {                                            \
            if (acc != 0.0f) atomicAdd(&out[seg], acc);                    \
            acc = 0.0f;                                                    \
            do { seg++; } while ((EIDX) >= sbnd[seg + 1]);                 \
            bndEnd = sbnd[seg + 1];                                        \
        }                                                                  \
        acc += (VVAL);                                                     \
    } while (0)

// Warp-aggregated final flush: one atomic per warp when segment is uniform.
__device__ __forceinline__ void flush_acc(float* __restrict__ out, int seg, float acc)
{
    const unsigned full = 0xFFFFFFFFu;
    int seg0 = __shfl_sync(full, seg, 0);
    bool uniform = __all_sync(full, seg == seg0);
    if (uniform) {
        #pragma unroll
        for (int o = 16; o > 0; o >>= 1)
            acc += __shfl_xor_sync(full, acc, o);
        if ((threadIdx.x & 31) == 0 && acc != 0.0f)
            atomicAdd(&out[seg0], acc);
    } else {
        if (acc != 0.0f) atomicAdd(&out[seg], acc);
    }
}

// ---------------------------------------------------------------------------
// Main int32 edge kernel
// ---------------------------------------------------------------------------
__global__ void __launch_bounds__(TPB, 7)
edge_kernel32(const int* __restrict__ map0,
              const int* __restrict__ map1,
              const float* __restrict__ ks,     // [4,25,25]
              const float* __restrict__ v0t,    // [25,25]
              float* __restrict__ out,
              int E, int G)
{
    if (read_flag() != 0) return;

    __shared__ float4 sk[TT];
    __shared__ float  sv[TT];
    __shared__ int    sbnd[GMAX + 1];

    const int tid = threadIdx.x;
    for (int i = tid; i < TT; i += TPB) {
        sk[i] = make_float4(ks[i], ks[TT + i], ks[2 * TT + i], ks[3 * TT + i]);
        sv[i] = v0t[i];
    }
    for (int i = tid; i <= G; i += TPB) sbnd[i] = g_bnd[i];
    __syncthreads();

    const int tile = blockIdx.x * TILE;
    if (tile >= E) return;

    // initial segment for this thread's first edge
    int firstE = tile + tid * VEC;
    if (firstE >= E) firstE = E - 1;
    int lo = 0, hi = G - 1;
    while (lo < hi) {
        int mid = (lo + hi) >> 1;
        if (sbnd[mid + 1] <= firstE) lo = mid + 1; else hi = mid;
    }
    int   seg    = lo;
    int   bndEnd = sbnd[seg + 1];
    float acc    = 0.0f;

    const float4* __restrict__ nodes = g_nodes;

    if (tile + TILE <= E) {
        #pragma unroll
        for (int it = 0; it < ITERS; ++it) {
            const int e = tile + it * (TPB * VEC) + tid * VEC;
            int4 ia = __ldcs((const int4*)(map0 + e));
            int4 ja = __ldcs((const int4*)(map1 + e));

            float V0, V1, V2, V3;
            EDGE_V(ia.x, ja.x, V0);
            EDGE_V(ia.y, ja.y, V1);
            EDGE_V(ia.z, ja.z, V2);
            EDGE_V(ia.w, ja.w, V3);

            if (e + 3 < bndEnd) {
                acc += (V0 + V1) + (V2 + V3);
            } else {
                HANDLE1(e + 0, V0);
                HANDLE1(e + 1, V1);
                HANDLE1(e + 2, V2);
                HANDLE1(e + 3, V3);
            }
        }
    } else {
        for (int it = 0; it < ITERS; ++it) {
            int e = tile + it * (TPB * VEC) + tid * VEC;
            for (int kk = 0; kk < VEC; ++kk) {
                int ee = e + kk;
                if (ee >= E) break;
                int ii = __ldcs(map0 + ee);
                int jj = __ldcs(map1 + ee);
                float V;
                EDGE_V(ii, jj, V);
                HANDLE1(ee, V);
            }
        }
    }

    flush_acc(out, seg, acc);
}

// ---------------------------------------------------------------------------
// int64 fallback (early-exits when data is int32)
// ---------------------------------------------------------------------------
__global__ void __launch_bounds__(TPB)
edge_kernel64(const long long* __restrict__ map0,
              const long long* __restrict__ map1,
              const float* __restrict__ ks,
              const float* __restrict__ v0t,
              float* __restrict__ out,
              int E, int G)
{
    if (read_flag() != 1) return;

    __shared__ float4 sk[TT];
    __shared__ float  sv[TT];
    __shared__ int    sbnd[GMAX + 1];

    const int tid = threadIdx.x;
    for (int i = tid; i < TT; i += TPB) {
        sk[i] = make_float4(ks[i], ks[TT + i], ks[2 * TT + i], ks[3 * TT + i]);
        sv[i] = v0t[i];
    }
    for (int i = tid; i <= G; i += TPB) sbnd[i] = g_bnd[i];
    __syncthreads();

    const int tile = blockIdx.x * TILE;
    if (tile >= E) return;

    int firstE = tile + tid * VEC;
    if (firstE >= E) firstE = E - 1;
    int lo = 0, hi = G - 1;
    while (lo < hi) {
        int mid = (lo + hi) >> 1;
        if (sbnd[mid + 1] <= firstE) lo = mid + 1; else hi = mid;
    }
    int   seg    = lo;
    int   bndEnd = sbnd[seg + 1];
    float acc    = 0.0f;

    const float4* __restrict__ nodes = g_nodes;

    for (int it = 0; it < ITERS; ++it) {
        int e = tile + it * (TPB * VEC) + tid * VEC;
        if (e >= E) break;
        if (e + VEC <= E) {
            longlong2 a0 = __ldcs((const longlong2*)(map0 + e));
            longlong2 a1 = __ldcs((const longlong2*)(map0 + e + 2));
            longlong2 b0 = __ldcs((const longlong2*)(map1 + e));
            longlong2 b1 = __ldcs((const longlong2*)(map1 + e + 2));
            float V0, V1, V2, V3;
            EDGE_V((int)a0.x, (int)b0.x, V0);
            EDGE_V((int)a0.y, (int)b0.y, V1);
            EDGE_V((int)a1.x, (int)b1.x, V2);
            EDGE_V((int)a1.y, (int)b1.y, V3);
            if (e + 3 < bndEnd) {
                acc += (V0 + V1) + (V2 + V3);
            } else {
                HANDLE1(e + 0, V0);
                HANDLE1(e + 1, V1);
                HANDLE1(e + 2, V2);
                HANDLE1(e + 3, V3);
            }
        } else {
            for (int kk = 0; kk < VEC; ++kk) {
                int ee = e + kk;
                if (ee >= E) break;
                int ii = (int)__ldcs(map0 + ee);
                int jj = (int)__ldcs(map1 + ee);
                float V;
                EDGE_V(ii, jj, V);
                HANDLE1(ee, V);
            }
        }
    }
    if (acc != 0.0f) atomicAdd(&out[seg], acc);
}

// ---------------------------------------------------------------------------
// Launch
// ---------------------------------------------------------------------------
extern "C" void kernel_launch(void* const* d_in, const int* in_sizes, int n_in,
                              void* d_out, int out_size)
{
    const float* pos = (const float*)d_in[0];
    const float* ks  = (const float*)d_in[1];
    const float* v0t = (const float*)d_in[2];
    const void*  mapping    = d_in[3];
    const void*  atom_types = d_in[4];
    const void*  batch      = d_in[5];

    const int N = in_sizes[0] / 3;
    const int E = in_sizes[3] / 2;
    const int G = out_size;

    float* out = (float*)d_out;

    detect_kernel<<<1, 1>>>((const long long*)mapping, N);

    int prepThreads = (N > G + 1) ? N : (G + 1);
    int prepBlocks  = (prepThreads + TPB - 1) / TPB;
    prep_kernel<int><<<prepBlocks, TPB>>>(
        pos, (const int*)atom_types, (const int*)batch, out, N, E, G, 0);
    prep_kernel<long long><<<prepBlocks, TPB>>>(
        pos, (const long long*)atom_types, (const long long*)batch, out, N, E, G, 1);

    int blocks = (E + TILE - 1) / TILE;
    edge_kernel32<<<blocks, TPB>>>(
        (const int*)mapping, (const int*)mapping + E, ks, v0t, out, E, G);
    edge_kernel64<<<blocks, TPB>>>(
        (const long long*)mapping, (const long long*)mapping + E, ks, v0t, out, E, G);
}